// round 4
// baseline (speedup 1.0000x reference)
#include <cuda_runtime.h>

#define N_NODES 100000
#define D 128
#define N_EDGES 1600000

// Scratch (__device__ globals per allocation rules)
__device__ float g_Y[(size_t)N_NODES * D];                // x @ W   (51.2 MB)
__device__ int g_cnt[N_NODES];                            // histogram
__device__ int g_start[N_NODES + 1];                      // CSR offsets
__device__ int g_ptr[N_NODES];                            // placement cursors
__device__ unsigned long long g_edge[N_EDGES];            // packed (val:hi32, src:lo32)

// ---------------------------------------------------------------------------
// Counting sort stage 1: zero histogram
// ---------------------------------------------------------------------------
__global__ void __launch_bounds__(256) zero_cnt_kernel() {
    int i = blockIdx.x * 256 + threadIdx.x;
    if (i < N_NODES) g_cnt[i] = 0;
}

// Stage 2: histogram of dst
__global__ void __launch_bounds__(256) hist_kernel(const int* __restrict__ dst) {
    int e = blockIdx.x * 256 + threadIdx.x;
    if (e < N_EDGES) atomicAdd(&g_cnt[dst[e]], 1);
}

// Stage 3: exclusive scan (single block, 1024 threads, ~98 elems/thread)
__global__ void __launch_bounds__(1024) scan_kernel() {
    __shared__ int part[1024];
    const int t = threadIdx.x;
    const int chunk = (N_NODES + 1023) / 1024;   // 98
    const int lo = t * chunk;
    const int hi = min(lo + chunk, N_NODES);

    int s = 0;
    for (int i = lo; i < hi; i++) s += g_cnt[i];
    part[t] = s;
    __syncthreads();

    for (int off = 1; off < 1024; off <<= 1) {
        int v = (t >= off) ? part[t - off] : 0;
        __syncthreads();
        part[t] += v;
        __syncthreads();
    }

    int run = (t == 0) ? 0 : part[t - 1];
    for (int i = lo; i < hi; i++) {
        g_start[i] = run;
        g_ptr[i]   = run;
        run += g_cnt[i];
    }
    if (t == 1023) g_start[N_NODES] = N_EDGES;
}

// Stage 4: place edges into dst-sorted order, packing (val, src)
__global__ void __launch_bounds__(256) place_kernel(const int*   __restrict__ src,
                                                    const int*   __restrict__ dst,
                                                    const float* __restrict__ val) {
    int e = blockIdx.x * 256 + threadIdx.x;
    if (e >= N_EDGES) return;
    int d = dst[e];
    int pos = atomicAdd(&g_ptr[d], 1);
    unsigned long long p =
        ((unsigned long long)__float_as_uint(val[e]) << 32) | (unsigned)src[e];
    g_edge[pos] = p;
}

// ---------------------------------------------------------------------------
// GEMM: Y = x @ W   (x: [N_NODES, 128], W: [128, 128])
// ---------------------------------------------------------------------------
constexpr int BR = 32;

__global__ void __launch_bounds__(256) gemm_kernel(const float* __restrict__ x,
                                                   const float* __restrict__ w) {
    __shared__ float xs[BR][D];
    const int row0 = blockIdx.x * BR;

    const float4* xin = (const float4*)(x + (size_t)row0 * D);
    float4* xs4 = (float4*)xs;
#pragma unroll
    for (int i = 0; i < (BR * D / 4) / 256; i++)
        xs4[threadIdx.x + i * 256] = xin[threadIdx.x + i * 256];
    __syncthreads();

    const int lane = threadIdx.x & 31;
    const int warp = threadIdx.x >> 5;

    float4 acc0 = make_float4(0.f, 0.f, 0.f, 0.f);
    float4 acc1 = acc0, acc2 = acc0, acc3 = acc0;

    const float* x0 = xs[warp];
    const float* x1 = xs[warp + 8];
    const float* x2 = xs[warp + 16];
    const float* x3 = xs[warp + 24];
    const float4* wrow = (const float4*)w + lane;

#pragma unroll 8
    for (int k = 0; k < D; k++) {
        float4 wv = wrow[k * 32];
        float a0 = x0[k], a1 = x1[k], a2 = x2[k], a3 = x3[k];
        acc0.x += a0 * wv.x; acc0.y += a0 * wv.y; acc0.z += a0 * wv.z; acc0.w += a0 * wv.w;
        acc1.x += a1 * wv.x; acc1.y += a1 * wv.y; acc1.z += a1 * wv.z; acc1.w += a1 * wv.w;
        acc2.x += a2 * wv.x; acc2.y += a2 * wv.y; acc2.z += a2 * wv.z; acc2.w += a2 * wv.w;
        acc3.x += a3 * wv.x; acc3.y += a3 * wv.y; acc3.z += a3 * wv.z; acc3.w += a3 * wv.w;
    }

    float4* yout = (float4*)g_Y;
    yout[(size_t)(row0 + warp)      * 32 + lane] = acc0;
    yout[(size_t)(row0 + warp + 8)  * 32 + lane] = acc1;
    yout[(size_t)(row0 + warp + 16) * 32 + lane] = acc2;
    yout[(size_t)(row0 + warp + 24) * 32 + lane] = acc3;
}

// ---------------------------------------------------------------------------
// Gather: one warp per dst node. 4-way unrolled with 4 independent
// accumulators -> 4 Y-row loads in flight per warp (MLP=4) instead of a
// serial load->fma chain. Single plain float4 store per node.
// ---------------------------------------------------------------------------
__global__ void __launch_bounds__(512) gather_kernel(float* __restrict__ z) {
    const int node = blockIdx.x * 16 + (threadIdx.x >> 5);
    const int lane = threadIdx.x & 31;

    const int beg = g_start[node];
    const int end = g_start[node + 1];
    const int n   = end - beg;

    const float4* Y4 = (const float4*)g_Y;
    const unsigned long long* ep = g_edge + beg;

    float4 acc0 = make_float4(0.f, 0.f, 0.f, 0.f);
    float4 acc1 = acc0, acc2 = acc0, acc3 = acc0;

    int i = 0;
    for (; i + 4 <= n; i += 4) {
        // Batch-load 4 edge words (uniform broadcast), then issue 4
        // independent Y-row loads before any FMA consumes them.
        unsigned long long p0 = __ldg(ep + i);
        unsigned long long p1 = __ldg(ep + i + 1);
        unsigned long long p2 = __ldg(ep + i + 2);
        unsigned long long p3 = __ldg(ep + i + 3);

        float4 m0 = Y4[(size_t)(unsigned)(p0 & 0xffffffffu) * 32 + lane];
        float4 m1 = Y4[(size_t)(unsigned)(p1 & 0xffffffffu) * 32 + lane];
        float4 m2 = Y4[(size_t)(unsigned)(p2 & 0xffffffffu) * 32 + lane];
        float4 m3 = Y4[(size_t)(unsigned)(p3 & 0xffffffffu) * 32 + lane];

        float v0 = __uint_as_float((unsigned)(p0 >> 32));
        float v1 = __uint_as_float((unsigned)(p1 >> 32));
        float v2 = __uint_as_float((unsigned)(p2 >> 32));
        float v3 = __uint_as_float((unsigned)(p3 >> 32));

        acc0.x += v0 * m0.x; acc0.y += v0 * m0.y; acc0.z += v0 * m0.z; acc0.w += v0 * m0.w;
        acc1.x += v1 * m1.x; acc1.y += v1 * m1.y; acc1.z += v1 * m1.z; acc1.w += v1 * m1.w;
        acc2.x += v2 * m2.x; acc2.y += v2 * m2.y; acc2.z += v2 * m2.z; acc2.w += v2 * m2.w;
        acc3.x += v3 * m3.x; acc3.y += v3 * m3.y; acc3.z += v3 * m3.z; acc3.w += v3 * m3.w;
    }
    for (; i < n; i++) {
        unsigned long long p = __ldg(ep + i);
        float4 m = Y4[(size_t)(unsigned)(p & 0xffffffffu) * 32 + lane];
        float v = __uint_as_float((unsigned)(p >> 32));
        acc0.x += v * m.x; acc0.y += v * m.y; acc0.z += v * m.z; acc0.w += v * m.w;
    }

    acc0.x += acc1.x + acc2.x + acc3.x;
    acc0.y += acc1.y + acc2.y + acc3.y;
    acc0.z += acc1.z + acc2.z + acc3.z;
    acc0.w += acc1.w + acc2.w + acc3.w;

    ((float4*)z)[(size_t)node * 32 + lane] = acc0;
}

// ---------------------------------------------------------------------------
// Launch
// ---------------------------------------------------------------------------
extern "C" void kernel_launch(void* const* d_in, const int* in_sizes, int n_in,
                              void* d_out, int out_size) {
    const float* x   = (const float*)d_in[0];
    const float* w   = (const float*)d_in[1];
    const int*   src = (const int*)  d_in[2];
    const int*   dst = (const int*)  d_in[3];
    const float* val = (const float*)d_in[4];
    float*       z   = (float*)d_out;

    zero_cnt_kernel<<<(N_NODES + 255) / 256, 256>>>();
    hist_kernel<<<(N_EDGES + 255) / 256, 256>>>(dst);
    scan_kernel<<<1, 1024>>>();
    place_kernel<<<(N_EDGES + 255) / 256, 256>>>(src, dst, val);
    gemm_kernel<<<N_NODES / BR, 256>>>(x, w);
    gather_kernel<<<(N_NODES + 15) / 16, 512>>>(z);
}

// round 5
// speedup vs baseline: 1.2315x; 1.2315x over previous
#include <cuda_runtime.h>

#define N_NODES 100000
#define D 128
#define N_EDGES 1600000

// Scratch: Y = x @ W  (51.2 MB)
__device__ float g_Y[(size_t)N_NODES * D];

// ---------------------------------------------------------------------------
// Zero output (harness poisons d_out)
// ---------------------------------------------------------------------------
__global__ void __launch_bounds__(256) zero_kernel(float4* __restrict__ z) {
    size_t i = (size_t)blockIdx.x * blockDim.x + threadIdx.x;
    z[i] = make_float4(0.f, 0.f, 0.f, 0.f);
}

// ---------------------------------------------------------------------------
// tf32 helpers
// ---------------------------------------------------------------------------
__device__ __forceinline__ unsigned f2tf32(float f) {
    unsigned r;
    asm("cvt.rna.tf32.f32 %0, %1;" : "=r"(r) : "f"(f));
    return r;
}

__device__ __forceinline__ void mma_tf32(float& d0, float& d1, float& d2, float& d3,
                                         unsigned a0, unsigned a1, unsigned a2, unsigned a3,
                                         unsigned b0, unsigned b1) {
    asm volatile(
        "mma.sync.aligned.m16n8k8.row.col.f32.tf32.tf32.f32 "
        "{%0,%1,%2,%3}, {%4,%5,%6,%7}, {%8,%9}, {%0,%1,%2,%3};"
        : "+f"(d0), "+f"(d1), "+f"(d2), "+f"(d3)
        : "r"(a0), "r"(a1), "r"(a2), "r"(a3), "r"(b0), "r"(b1));
}

// ---------------------------------------------------------------------------
// Tensor-core GEMM: Y = x @ W  via m16n8k8 tf32.
// Block = 256 thr (8 warps), tile = 32 rows x 128 cols. grid = 3125 (exact).
// smem: W [128][132] padded (conflict-free B frags), x tile [32][132].
// Warp (w>>2) picks m-half (16 rows), (w&3) picks 32-col quarter (4 n-tiles).
// ---------------------------------------------------------------------------
#define WS_STRIDE 132
extern __shared__ unsigned gemm_smem[];   // ws[128*132] then xs[32*132]

__global__ void __launch_bounds__(256) gemm_tc_kernel(const float* __restrict__ x,
                                                      const float* __restrict__ w) {
    unsigned* ws = gemm_smem;                     // 128*132
    unsigned* xs = gemm_smem + 128 * WS_STRIDE;   // 32*132

    const int tid = threadIdx.x;
    const int row0 = blockIdx.x * 32;

    // Fill W (16384 elems, 64 per thread, coalesced reads)
#pragma unroll
    for (int i = tid; i < 128 * 128; i += 256) {
        int k = i >> 7, n = i & 127;
        ws[k * WS_STRIDE + n] = f2tf32(w[i]);
    }
    // Fill x tile (4096 elems, 16 per thread)
#pragma unroll
    for (int i = tid; i < 32 * 128; i += 256) {
        int r = i >> 7, c = i & 127;
        xs[r * WS_STRIDE + c] = f2tf32(x[(size_t)(row0 + r) * D + c]);
    }
    __syncthreads();

    const int lane = tid & 31;
    const int warp = tid >> 5;
    const int g = lane >> 2;        // group id 0..7
    const int t = lane & 3;         // thread-in-group 0..3
    const int m0 = (warp >> 2) * 16;        // 0 or 16
    const int nb = (warp & 3) * 32;         // 0,32,64,96

    float d[4][4];
#pragma unroll
    for (int j = 0; j < 4; j++)
        d[j][0] = d[j][1] = d[j][2] = d[j][3] = 0.f;

#pragma unroll
    for (int k0 = 0; k0 < 128; k0 += 8) {
        // A fragment (m16 x k8), rows m0..m0+15
        unsigned a0 = xs[(m0 + g) * WS_STRIDE + k0 + t];
        unsigned a1 = xs[(m0 + g + 8) * WS_STRIDE + k0 + t];
        unsigned a2 = xs[(m0 + g) * WS_STRIDE + k0 + t + 4];
        unsigned a3 = xs[(m0 + g + 8) * WS_STRIDE + k0 + t + 4];
#pragma unroll
        for (int j = 0; j < 4; j++) {
            int n0 = nb + j * 8;
            unsigned b0 = ws[(k0 + t) * WS_STRIDE + n0 + g];
            unsigned b1 = ws[(k0 + t + 4) * WS_STRIDE + n0 + g];
            mma_tf32(d[j][0], d[j][1], d[j][2], d[j][3], a0, a1, a2, a3, b0, b1);
        }
    }

    // Store: d0,d1 -> (row m0+g, col n0+2t..+1); d2,d3 -> row+8
    float2* y2 = (float2*)g_Y;
#pragma unroll
    for (int j = 0; j < 4; j++) {
        int n0 = nb + j * 8;
        size_t r0 = (size_t)(row0 + m0 + g) * 64 + (n0 >> 1) + t;
        size_t r1 = (size_t)(row0 + m0 + g + 8) * 64 + (n0 >> 1) + t;
        y2[r0] = make_float2(d[j][0], d[j][1]);
        y2[r1] = make_float2(d[j][2], d[j][3]);
    }
}

// ---------------------------------------------------------------------------
// Vector reduction scatter (proven R2 config): one warp per edge,
// float4 gather of Y[src] + one red.global.add.v4.f32 to Z[dst].
// ---------------------------------------------------------------------------
__device__ __forceinline__ void red_add_v4(float* ptr, float a, float b,
                                           float c, float d) {
    asm volatile("red.global.add.v4.f32 [%0], {%1, %2, %3, %4};"
                 :: "l"(ptr), "f"(a), "f"(b), "f"(c), "f"(d)
                 : "memory");
}

__global__ void __launch_bounds__(256) scatter_kernel(const int*   __restrict__ src,
                                                      const int*   __restrict__ dst,
                                                      const float* __restrict__ val,
                                                      float*       __restrict__ z) {
    const int e = (int)(((size_t)blockIdx.x * blockDim.x + threadIdx.x) >> 5);
    if (e >= N_EDGES) return;
    const int lane = threadIdx.x & 31;

    const int   s = __ldg(src + e);
    const int   d = __ldg(dst + e);
    const float v = __ldg(val + e);

    float4 m = ((const float4*)(g_Y + (size_t)s * D))[lane];
    float* zr = z + (size_t)d * D + lane * 4;
    red_add_v4(zr, v * m.x, v * m.y, v * m.z, v * m.w);
}

// ---------------------------------------------------------------------------
// Launch
// ---------------------------------------------------------------------------
extern "C" void kernel_launch(void* const* d_in, const int* in_sizes, int n_in,
                              void* d_out, int out_size) {
    const float* x   = (const float*)d_in[0];
    const float* w   = (const float*)d_in[1];
    const int*   src = (const int*)  d_in[2];
    const int*   dst = (const int*)  d_in[3];
    const float* val = (const float*)d_in[4];
    float*       z   = (float*)d_out;

    const int smem_bytes = (128 * WS_STRIDE + 32 * WS_STRIDE) * 4;  // 84480
    cudaFuncSetAttribute(gemm_tc_kernel,
                         cudaFuncAttributeMaxDynamicSharedMemorySize, smem_bytes);

    zero_kernel<<<(N_NODES * D / 4) / 256, 256>>>((float4*)z);
    gemm_tc_kernel<<<N_NODES / 32, 256, smem_bytes>>>(x, w);
    scatter_kernel<<<((size_t)N_EDGES * 32) / 256, 256>>>(src, dst, val, z);
}

// round 6
// speedup vs baseline: 1.2820x; 1.0410x over previous
#include <cuda_runtime.h>
#include <cuda_fp16.h>

#define N_NODES 100000
#define D 128
#define N_EDGES 1600000

// Scratch: Y = x @ W stored in fp16 (25.6 MB) — halves scatter read traffic.
__device__ __half g_Yh[(size_t)N_NODES * D];

// ---------------------------------------------------------------------------
// Zero output (harness poisons d_out)
// ---------------------------------------------------------------------------
__global__ void __launch_bounds__(256) zero_kernel(float4* __restrict__ z) {
    size_t i = (size_t)blockIdx.x * blockDim.x + threadIdx.x;
    z[i] = make_float4(0.f, 0.f, 0.f, 0.f);
}

// ---------------------------------------------------------------------------
// tf32 helpers
// ---------------------------------------------------------------------------
__device__ __forceinline__ unsigned f2tf32(float f) {
    unsigned r;
    asm("cvt.rna.tf32.f32 %0, %1;" : "=r"(r) : "f"(f));
    return r;
}

__device__ __forceinline__ void mma_tf32(float& d0, float& d1, float& d2, float& d3,
                                         unsigned a0, unsigned a1, unsigned a2, unsigned a3,
                                         unsigned b0, unsigned b1) {
    asm volatile(
        "mma.sync.aligned.m16n8k8.row.col.f32.tf32.tf32.f32 "
        "{%0,%1,%2,%3}, {%4,%5,%6,%7}, {%8,%9}, {%0,%1,%2,%3};"
        : "+f"(d0), "+f"(d1), "+f"(d2), "+f"(d3)
        : "r"(a0), "r"(a1), "r"(a2), "r"(a3), "r"(b0), "r"(b1));
}

// ---------------------------------------------------------------------------
// Tensor-core GEMM: Y = x @ W, 64 rows per block (grid 1563) to amortize the
// per-block W smem fill 2x vs R5's 32-row tiles (W reload 200MB -> 100MB).
// Warp w: m-group (w>>1)*16, n-half (w&1)*64 -> m16 x n64 per warp
// (8 MMA per 20 LDS per k-chunk vs 4 per 12 before).
// ---------------------------------------------------------------------------
#define WS_STRIDE 132
#define GEMM_ROWS 64
extern __shared__ unsigned gemm_smem[];   // ws[128*132] then xs[64*132]

__global__ void __launch_bounds__(256) gemm_tc_kernel(const float* __restrict__ x,
                                                      const float* __restrict__ w) {
    unsigned* ws = gemm_smem;                       // 128*132
    unsigned* xs = gemm_smem + 128 * WS_STRIDE;     // 64*132

    const int tid = threadIdx.x;
    const int row0 = blockIdx.x * GEMM_ROWS;

    // Fill W (16384 elems, 64 per thread)
#pragma unroll
    for (int i = tid; i < 128 * 128; i += 256) {
        int k = i >> 7, n = i & 127;
        ws[k * WS_STRIDE + n] = f2tf32(w[i]);
    }
    // Fill x tile (8192 elems, 32 per thread), zero OOB rows
#pragma unroll
    for (int i = tid; i < GEMM_ROWS * 128; i += 256) {
        int r = i >> 7, c = i & 127;
        int gr = row0 + r;
        float xv = (gr < N_NODES) ? x[(size_t)gr * D + c] : 0.f;
        xs[r * WS_STRIDE + c] = f2tf32(xv);
    }
    __syncthreads();

    const int lane = tid & 31;
    const int warp = tid >> 5;
    const int g = lane >> 2;                 // 0..7
    const int t = lane & 3;                  // 0..3
    const int m0 = (warp >> 1) * 16;         // 0,16,32,48
    const int nb = (warp & 1) * 64;          // 0 or 64

    float d[8][4];
#pragma unroll
    for (int j = 0; j < 8; j++)
        d[j][0] = d[j][1] = d[j][2] = d[j][3] = 0.f;

#pragma unroll
    for (int k0 = 0; k0 < 128; k0 += 8) {
        unsigned a0 = xs[(m0 + g) * WS_STRIDE + k0 + t];
        unsigned a1 = xs[(m0 + g + 8) * WS_STRIDE + k0 + t];
        unsigned a2 = xs[(m0 + g) * WS_STRIDE + k0 + t + 4];
        unsigned a3 = xs[(m0 + g + 8) * WS_STRIDE + k0 + t + 4];
#pragma unroll
        for (int j = 0; j < 8; j++) {
            int n0 = nb + j * 8;
            unsigned b0 = ws[(k0 + t) * WS_STRIDE + n0 + g];
            unsigned b1 = ws[(k0 + t + 4) * WS_STRIDE + n0 + g];
            mma_tf32(d[j][0], d[j][1], d[j][2], d[j][3], a0, a1, a2, a3, b0, b1);
        }
    }

    // Store as fp16: d0,d1 -> (row m0+g, cols n0+2t,+1); d2,d3 -> row+8
    __half2* y2 = (__half2*)g_Yh;
    const int r0 = row0 + m0 + g;
    const int r1 = r0 + 8;
#pragma unroll
    for (int j = 0; j < 8; j++) {
        int n0 = nb + j * 8;
        if (r0 < N_NODES)
            y2[(size_t)r0 * 64 + (n0 >> 1) + t] = __floats2half2_rn(d[j][0], d[j][1]);
        if (r1 < N_NODES)
            y2[(size_t)r1 * 64 + (n0 >> 1) + t] = __floats2half2_rn(d[j][2], d[j][3]);
    }
}

// ---------------------------------------------------------------------------
// Scatter: one warp per edge. Lane l reads Y[src] halves 4l..4l+3 (8B uint2,
// 256B/warp -> half the read sectors of fp32), converts to fp32, one
// red.global.add.v4.f32 to Z[dst].
// ---------------------------------------------------------------------------
__device__ __forceinline__ void red_add_v4(float* ptr, float a, float b,
                                           float c, float d) {
    asm volatile("red.global.add.v4.f32 [%0], {%1, %2, %3, %4};"
                 :: "l"(ptr), "f"(a), "f"(b), "f"(c), "f"(d)
                 : "memory");
}

__global__ void __launch_bounds__(256) scatter_kernel(const int*   __restrict__ src,
                                                      const int*   __restrict__ dst,
                                                      const float* __restrict__ val,
                                                      float*       __restrict__ z) {
    const int e = (int)(((size_t)blockIdx.x * blockDim.x + threadIdx.x) >> 5);
    if (e >= N_EDGES) return;
    const int lane = threadIdx.x & 31;

    const int   s = __ldg(src + e);
    const int   d = __ldg(dst + e);
    const float v = __ldg(val + e);

    uint2 raw = *(const uint2*)(g_Yh + (size_t)s * D + lane * 4);
    float2 f01 = __half22float2(*(const __half2*)&raw.x);
    float2 f23 = __half22float2(*(const __half2*)&raw.y);

    float* zr = z + (size_t)d * D + lane * 4;
    red_add_v4(zr, v * f01.x, v * f01.y, v * f23.x, v * f23.y);
}

// ---------------------------------------------------------------------------
// Launch
// ---------------------------------------------------------------------------
extern "C" void kernel_launch(void* const* d_in, const int* in_sizes, int n_in,
                              void* d_out, int out_size) {
    const float* x   = (const float*)d_in[0];
    const float* w   = (const float*)d_in[1];
    const int*   src = (const int*)  d_in[2];
    const int*   dst = (const int*)  d_in[3];
    const float* val = (const float*)d_in[4];
    float*       z   = (float*)d_out;

    const int smem_bytes = (128 * WS_STRIDE + GEMM_ROWS * WS_STRIDE) * 4;  // 101376
    cudaFuncSetAttribute(gemm_tc_kernel,
                         cudaFuncAttributeMaxDynamicSharedMemorySize, smem_bytes);

    zero_kernel<<<(N_NODES * D / 4) / 256, 256>>>((float4*)z);
    gemm_tc_kernel<<<(N_NODES + GEMM_ROWS - 1) / GEMM_ROWS, 256, smem_bytes>>>(x, w);
    scatter_kernel<<<((size_t)N_EDGES * 32) / 256, 256>>>(src, dst, val, z);
}